// round 17
// baseline (speedup 1.0000x reference)
#include <cuda_runtime.h>
#include <cuda_fp16.h>
#include <math.h>
#include <stdint.h>

// Problem constants
#define BB 8
#define TT 4096
#define NM 1024
#define HS 128
#define MROWS (BB * TT)
#define NQT64 (TT / 64)          // 64 query tiles of 64 rows

// Scratch: fp16 K/Q (RoPE'd, [b][t][h]) and fp16 V transposed ([b][h][t])
__device__ __half g_kh[MROWS * HS];
__device__ __half g_vt[MROWS * HS];

// ---------------------------------------------------------------------------
__device__ __forceinline__ float fast_exp2(float x) {
    float y;
    asm("ex2.approx.ftz.f32 %0, %1;" : "=f"(y) : "f"(x));
    return y;
}
__device__ __forceinline__ void mma_f16(float c[4],
                                        uint32_t a0, uint32_t a1, uint32_t a2, uint32_t a3,
                                        uint32_t b0, uint32_t b1) {
    asm volatile(
        "mma.sync.aligned.m16n8k16.row.col.f32.f16.f16.f32 "
        "{%0,%1,%2,%3}, {%4,%5,%6,%7}, {%8,%9}, {%0,%1,%2,%3};\n"
        : "+f"(c[0]), "+f"(c[1]), "+f"(c[2]), "+f"(c[3])
        : "r"(a0), "r"(a1), "r"(a2), "r"(a3), "r"(b0), "r"(b1));
}
__device__ __forceinline__ uint32_t packh2(float lo, float hi) {
    half2 h = __floats2half2_rn(lo, hi);     // .x = lo (low half)
    return *(uint32_t*)&h;
}
__device__ __forceinline__ void cpa16(uint32_t saddr, const void* g) {
    asm volatile("cp.async.cg.shared.global [%0], [%1], 16;" :: "r"(saddr), "l"(g));
}
__device__ __forceinline__ void cpa_commit() {
    asm volatile("cp.async.commit_group;");
}
#define LDSM4(r0, r1, r2, r3, a) \
    asm volatile("ldmatrix.sync.aligned.m8n8.x4.shared.b16 {%0,%1,%2,%3}, [%4];" \
                 : "=r"(r0), "=r"(r1), "=r"(r2), "=r"(r3) : "r"(a))
#define FU(x) __float_as_uint(x)

// ---------------------------------------------------------------------------
// Kernel 1: k = x @ W_K^T (fp16 mma m16n8k16, fp32 accum) fused with RoPE.
// fp16 staging has the SAME mantissa as tf32 -> identical rounding behavior.
// Epilogue writes g_kh (RoPE'd half, [b][t][h]) and g_vt (raw half, [b][h][t]).
// ---------------------------------------------------------------------------
#define STP 40   // halves per staging row (32 + 8 pad -> conflict-free frags)
__global__ __launch_bounds__(256) void proj_rope_kernel(
    const float* __restrict__ x, const float* __restrict__ W)
{
    __shared__ __align__(16) char PSM[34048];
    __half* Xh = (__half*)PSM;               // [128][STP]
    __half* Wh = Xh + 128 * STP;             // [128][STP]

    const int tid  = threadIdx.x;
    const int w    = tid >> 5;
    const int lane = tid & 31;
    const int g    = lane >> 2;
    const int tq   = lane & 3;
    const int m0   = blockIdx.x * 128;

    float o[16][4];
    #pragma unroll
    for (int nt = 0; nt < 16; nt++)
        #pragma unroll
        for (int r = 0; r < 4; r++) o[nt][r] = 0.f;

    for (int k0 = 0; k0 < NM; k0 += 32) {
        #pragma unroll
        for (int pass = 0; pass < 4; pass++) {
            int linear = pass * 1024 + tid * 4;
            int row = linear >> 5;
            int c   = linear & 31;
            float4 v = *(const float4*)&x[(size_t)(m0 + row) * NM + k0 + c];
            *(half2*)&Xh[row * STP + c    ] = __floats2half2_rn(v.x, v.y);
            *(half2*)&Xh[row * STP + c + 2] = __floats2half2_rn(v.z, v.w);
            float4 u = *(const float4*)&W[(size_t)row * NM + k0 + c];
            *(half2*)&Wh[row * STP + c    ] = __floats2half2_rn(u.x, u.y);
            *(half2*)&Wh[row * STP + c + 2] = __floats2half2_rn(u.z, u.w);
        }
        __syncthreads();

        #pragma unroll
        for (int kk = 0; kk < 2; kk++) {
            uint32_t a0 = *(const uint32_t*)&Xh[(w * 16 + g    ) * STP + kk * 16 + 2 * tq    ];
            uint32_t a1 = *(const uint32_t*)&Xh[(w * 16 + g + 8) * STP + kk * 16 + 2 * tq    ];
            uint32_t a2 = *(const uint32_t*)&Xh[(w * 16 + g    ) * STP + kk * 16 + 2 * tq + 8];
            uint32_t a3 = *(const uint32_t*)&Xh[(w * 16 + g + 8) * STP + kk * 16 + 2 * tq + 8];
            #pragma unroll
            for (int nt = 0; nt < 16; nt++) {
                uint32_t b0 = *(const uint32_t*)&Wh[(nt * 8 + g) * STP + kk * 16 + 2 * tq    ];
                uint32_t b1 = *(const uint32_t*)&Wh[(nt * 8 + g) * STP + kk * 16 + 2 * tq + 8];
                mma_f16(o[nt], a0, a1, a2, a3, b0, b1);
            }
        }
        __syncthreads();
    }

    // ---- epilogue: RoPE (in-place semantics) + V transpose ----
    const float THSC = -0.20762050f; // -log2(10000)/64
    const int r0 = m0 + w * 16 + g;
    const int r1 = r0 + 8;
    const int batch = m0 / TT;
    const int t0g   = m0 & (TT - 1);
    const int tl0   = w * 16 + g;          // local t of row r0

    __half* Vsm = (__half*)PSM;            // [128 h][132 t-local] halves

    #pragma unroll
    for (int nt = 0; nt < 16; nt++) {
        int p = nt * 4 + tq;
        float theta = fast_exp2((float)p * THSC);
        float sth, cth;
        __sincosf(theta, &sth, &cth);
        int h0 = nt * 8 + 2 * tq;
        Vsm[(h0    ) * 132 + tl0    ] = __float2half_rn(o[nt][0]);
        Vsm[(h0 + 1) * 132 + tl0    ] = __float2half_rn(o[nt][1]);
        Vsm[(h0    ) * 132 + tl0 + 8] = __float2half_rn(o[nt][2]);
        Vsm[(h0 + 1) * 132 + tl0 + 8] = __float2half_rn(o[nt][3]);
        {
            float t1 = o[nt][0], t2 = o[nt][1];
            float ev = t1 * cth + t2 * sth;
            float od = -ev * sth + t2 * cth;
            half2 h = __floats2half2_rn(ev, od);
            *(half2*)&g_kh[(size_t)r0 * HS + h0] = h;
        }
        {
            float t1 = o[nt][2], t2 = o[nt][3];
            float ev = t1 * cth + t2 * sth;
            float od = -ev * sth + t2 * cth;
            half2 h = __floats2half2_rn(ev, od);
            *(half2*)&g_kh[(size_t)r1 * HS + h0] = h;
        }
    }
    __syncthreads();

    {
        const size_t vbase = (size_t)batch * HS * TT;
        #pragma unroll
        for (int pass = 0; pass < 32; pass++) {
            int idx = pass * 256 + tid;       // 8192 half2
            int row = idx >> 6;               // h
            int c2  = idx & 63;               // half2 within row
            uint32_t v = *(uint32_t*)&Vsm[row * 132 + 2 * c2];
            *(uint32_t*)&g_vt[vbase + (size_t)row * TT + t0g + 2 * c2] = v;
        }
    }
}

// ---------------------------------------------------------------------------
// Kernel 2: causal flash attention, fp16 mma m16n8k16, fixed-base softmax.
// BM=64 (4 warps), BN=32, cp.async double-buffered K/V, ldmatrix.x4 B-frags.
// No P smem roundtrip. 37 KB smem, 3 CTAs/SM.
// K tiles: [32 key][136 half] (272B rows); V tiles: [128 h][40 half] (80B rows)
// ---------------------------------------------------------------------------
#define SKH 136
#define SVH 40
#define AK0 0
#define AK1 8704
#define AV0 17408
#define AV1 27648
#define SMEM_ATTN_BYTES 37888

__global__ __launch_bounds__(128, 3) void attn_kernel(float* __restrict__ out)
{
    extern __shared__ __align__(16) char smc[];

    const int tid  = threadIdx.x;
    const int w    = tid >> 5;       // 0..3
    const int lane = tid & 31;
    const int g    = lane >> 2;
    const int tq   = lane & 3;
    const int b    = blockIdx.x;                 // batch (fast axis)
    const int qi   = (NQT64 - 1) - blockIdx.y;   // heavy q-tiles first

    const __half* khb = g_kh + (size_t)b * TT * HS;
    const __half* vtb = g_vt + (size_t)b * HS * TT;
    const float C = 1.4426950408889634f * 0.08838834764831845f; // log2(e)/sqrt(128)

    uint32_t sb;
    asm("{ .reg .u64 t; cvta.to.shared.u64 t, %1; cvt.u32.u64 %0, t; }"
        : "=r"(sb) : "l"(smc));
    const int koff[2] = {AK0, AK1};
    const int voff[2] = {AV0, AV1};

    // ldmatrix lane offsets: row = (lane>>4)*8 + (lane&7), col = ((lane>>3)&1)*8
    const int lrow = ((lane >> 4) << 3) | (lane & 7);
    const int lcol = ((lane >> 3) & 1) * 8;
    const uint32_t kfo = (uint32_t)((lrow * SKH + lcol) * 2);
    const uint32_t vfo = (uint32_t)((lrow * SVH + lcol) * 2);

    // ---- prefetch K/V tile 0 ----
    {
        #pragma unroll
        for (int pass = 0; pass < 4; pass++) {
            int id  = pass * 128 + tid;          // 512 chunks each
            int key = id >> 4, c8 = id & 15;
            cpa16(sb + AK0 + key * 272 + c8 * 16, khb + key * HS + c8 * 8);
            int hd = id >> 2, c4 = id & 3;
            cpa16(sb + AV0 + hd * 80 + c4 * 16, vtb + (size_t)hd * TT + c4 * 8);
        }
        cpa_commit();
    }

    // ---- Q fragments (half2) straight from global (L2-resident) ----
    uint32_t qa[8][4];
    {
        const __half* q0 = khb + ((size_t)qi * 64 + w * 16 + g) * HS;
        const __half* q1 = q0 + 8 * HS;
        #pragma unroll
        for (int kk = 0; kk < 8; kk++) {
            qa[kk][0] = __ldg((const uint32_t*)(q0 + kk * 16 + 2 * tq    ));
            qa[kk][1] = __ldg((const uint32_t*)(q1 + kk * 16 + 2 * tq    ));
            qa[kk][2] = __ldg((const uint32_t*)(q0 + kk * 16 + 2 * tq + 8));
            qa[kk][3] = __ldg((const uint32_t*)(q1 + kk * 16 + 2 * tq + 8));
        }
    }

    float o[16][4];
    #pragma unroll
    for (int nt = 0; nt < 16; nt++)
        #pragma unroll
        for (int r = 0; r < 4; r++) o[nt][r] = 0.f;
    float l0 = 0.f, l1 = 0.f;

    const int nT = 2 * (qi + 1);       // k-tiles of 32 keys

    for (int jt = 0; jt < nT; jt++) {
        const int cur = jt & 1;
        if (jt + 1 < nT) {
            const int nb = cur ^ 1;
            const __half* ks = khb + (size_t)(jt + 1) * 32 * HS;
            const __half* vs = vtb + (size_t)(jt + 1) * 32;
            #pragma unroll
            for (int pass = 0; pass < 4; pass++) {
                int id  = pass * 128 + tid;
                int key = id >> 4, c8 = id & 15;
                cpa16(sb + koff[nb] + key * 272 + c8 * 16, ks + key * HS + c8 * 8);
                int hd = id >> 2, c4 = id & 3;
                cpa16(sb + voff[nb] + hd * 80 + c4 * 16, vs + (size_t)hd * TT + c4 * 8);
            }
            cpa_commit();
            asm volatile("cp.async.wait_group 1;");
        } else {
            asm volatile("cp.async.wait_group 0;");
        }
        __syncthreads();

        // ---- S = Q K^T  (64 rows x 32 keys), ldmatrix B-frags ----
        float sc[4][4];
        #pragma unroll
        for (int nt = 0; nt < 4; nt++)
            #pragma unroll
            for (int r = 0; r < 4; r++) sc[nt][r] = 0.f;

        const uint32_t kb = sb + koff[cur] + kfo;
        #pragma unroll
        for (int kk = 0; kk < 8; kk++) {
            #pragma unroll
            for (int ntp = 0; ntp < 2; ntp++) {
                uint32_t b0a, b1a, b0b, b1b;
                LDSM4(b0a, b1a, b0b, b1b,
                      kb + (uint32_t)(ntp * 16 * SKH * 2 + kk * 32));
                mma_f16(sc[2 * ntp    ], qa[kk][0], qa[kk][1], qa[kk][2], qa[kk][3], b0a, b1a);
                mma_f16(sc[2 * ntp + 1], qa[kk][0], qa[kk][1], qa[kk][2], qa[kk][3], b0b, b1b);
            }
        }

        // ---- fixed-base softmax + causal mask; pack P to half2 A-frags ----
        const bool nm = (jt >= 2 * qi);
        const int r0row = qi * 64 + w * 16 + g;
        const int r1row = r0row + 8;
        uint32_t hp[4][2];
        float ts0 = 0.f, ts1 = 0.f;
        #pragma unroll
        for (int nt = 0; nt < 4; nt++) {
            float p0 = fast_exp2(sc[nt][0] * C);
            float p1 = fast_exp2(sc[nt][1] * C);
            float p2 = fast_exp2(sc[nt][2] * C);
            float p3 = fast_exp2(sc[nt][3] * C);
            if (nm) {
                int c0 = jt * 32 + nt * 8 + 2 * tq, c1 = c0 + 1;
                if (c0 > r0row) p0 = 0.f;
                if (c1 > r0row) p1 = 0.f;
                if (c0 > r1row) p2 = 0.f;
                if (c1 > r1row) p3 = 0.f;
            }
            ts0 += p0 + p1; ts1 += p2 + p3;
            hp[nt][0] = packh2(p0, p1);    // row g
            hp[nt][1] = packh2(p2, p3);    // row g+8
        }
        l0 += ts0;
        l1 += ts1;

        // ---- O += P V  (A from registers, B via ldmatrix from Vt smem) ----
        const uint32_t vbse = sb + voff[cur] + vfo;
        #pragma unroll
        for (int kk2 = 0; kk2 < 2; kk2++) {
            uint32_t a0 = hp[2 * kk2    ][0];
            uint32_t a1 = hp[2 * kk2    ][1];
            uint32_t a2 = hp[2 * kk2 + 1][0];
            uint32_t a3 = hp[2 * kk2 + 1][1];
            #pragma unroll
            for (int ntp2 = 0; ntp2 < 8; ntp2++) {
                uint32_t b0a, b1a, b0b, b1b;
                LDSM4(b0a, b1a, b0b, b1b,
                      vbse + (uint32_t)(ntp2 * 16 * SVH * 2 + kk2 * 32));
                mma_f16(o[2 * ntp2    ], a0, a1, a2, a3, b0a, b1a);
                mma_f16(o[2 * ntp2 + 1], a0, a1, a2, a3, b0b, b1b);
            }
        }
        __syncthreads();   // all warps done with buf[cur] before overwrite
    }

    // ---- epilogue: reduce l across the quad, normalize, store ----
    l0 += __shfl_xor_sync(0xffffffffu, l0, 1);
    l0 += __shfl_xor_sync(0xffffffffu, l0, 2);
    l1 += __shfl_xor_sync(0xffffffffu, l1, 1);
    l1 += __shfl_xor_sync(0xffffffffu, l1, 2);
    float inv0 = 1.0f / l0;
    float inv1 = 1.0f / l1;
    size_t r0 = (size_t)b * TT + (size_t)qi * 64 + w * 16 + g;
    size_t r1 = r0 + 8;
    #pragma unroll
    for (int nt = 0; nt < 16; nt++) {
        float2 lo; lo.x = o[nt][0] * inv0; lo.y = o[nt][1] * inv0;
        float2 hi; hi.x = o[nt][2] * inv1; hi.y = o[nt][3] * inv1;
        *(float2*)&out[r0 * HS + nt * 8 + 2 * tq] = lo;
        *(float2*)&out[r1 * HS + nt * 8 + 2 * tq] = hi;
    }
}

// ---------------------------------------------------------------------------
extern "C" void kernel_launch(void* const* d_in, const int* in_sizes, int n_in,
                              void* d_out, int out_size)
{
    const float* x = (const float*)d_in[0];
    const float* W = (const float*)d_in[1];
    if (n_in >= 2 && in_sizes[0] < in_sizes[1]) {
        x = (const float*)d_in[1];
        W = (const float*)d_in[0];
    }

    cudaFuncSetAttribute(attn_kernel,
                         cudaFuncAttributeMaxDynamicSharedMemorySize,
                         SMEM_ATTN_BYTES);

    proj_rope_kernel<<<MROWS / 128, 256>>>(x, W);
    attn_kernel<<<dim3(BB, NQT64), 128, SMEM_ATTN_BYTES>>>((float*)d_out);
}